// round 3
// baseline (speedup 1.0000x reference)
#include <cuda_runtime.h>

#define DD   128
#define TM   64
#define NTHR 256
#define MAXN 100000

// Scratch (device globals — no runtime allocation allowed)
__device__ float g_agg[(size_t)MAXN * DD];
__device__ float g_colsum[DD];
__device__ float g_sumsq[1];
__device__ float g_mean[DD];
__device__ float g_invrms[1];

// Shared memory layout (floats):
//   Es   [64*33]     gathered input chunk (64 rows x 32 k, pad 33)
//   Ws   [32*128]    weight k-chunk
//   Hs   [64*132]    hidden / output tile (pad 132)
//   tail [132]       edge: 128 ints (src/dst); node: 129 floats (colsum + sumsq)
#define ES_OFF 0
#define WS_OFF (64*33)
#define HS_OFF (64*33 + 32*128)
#define TL_OFF (64*33 + 32*128 + 64*132)
#define SMEM_FLOATS (TL_OFF + 132)
#define SMEM_BYTES  (SMEM_FLOATS * 4)

static __device__ __forceinline__ void warp_red2(float& a, float& b) {
#pragma unroll
    for (int o = 16; o > 0; o >>= 1) {
        a += __shfl_xor_sync(0xffffffffu, a, o);
        b += __shfl_xor_sync(0xffffffffu, b, o);
    }
}

// ---------------------------------------------------------------------------
// Edge kernel: for 64 edges per block
//   e_in = [x[src], x[dst], edge_attr]  (384)
//   h = LN(relu(e_in@W1+b1)@W2+b2) * g + bt
//   edge_out = edge_attr + h          (written straight to d_out)
//   atomicAdd(agg[dst], h)            (segment_sum)
// ---------------------------------------------------------------------------
__global__ void edge_kernel(const float* __restrict__ x,
                            const float* __restrict__ ea,
                            const int* __restrict__ ei,
                            const float* __restrict__ W1, const float* __restrict__ b1,
                            const float* __restrict__ W2, const float* __restrict__ b2,
                            const float* __restrict__ gma, const float* __restrict__ bta,
                            float* __restrict__ eout, int E)
{
    extern __shared__ float sm[];
    float* Es = sm + ES_OFF;
    float* Ws = sm + WS_OFF;
    float* Hs = sm + HS_OFF;
    int*   sIdx = (int*)(sm + TL_OFF);   // [0..63]=src, [64..127]=dst

    const int tid  = threadIdx.x;
    const int eb   = blockIdx.x * TM;
    const int Eloc = min(TM, E - eb);

    if (tid < 64) {
        sIdx[tid] = (tid < Eloc) ? ei[eb + tid] : 0;
    } else if (tid < 128) {
        int t = tid - 64;
        sIdx[tid] = (t < Eloc) ? ei[E + eb + t] : 0;
    }
    __syncthreads();

    const int tm = tid >> 4, tn = tid & 15;
    const int m0 = tm * 4,  n0 = tn * 8;

    float acc[4][8];
#pragma unroll
    for (int i = 0; i < 4; i++)
#pragma unroll
        for (int j = 0; j < 8; j++) acc[i][j] = 0.f;

    // ---- GEMM1: [64 x 384] @ [384 x 128], 12 k-chunks of 32 ----
#pragma unroll 1
    for (int kc = 0; kc < 12; kc++) {
        const int k0   = kc * 32;
        const int seg  = k0 >> 7;     // 0: x[src], 1: x[dst], 2: edge_attr
        const int koff = k0 & 127;
#pragma unroll
        for (int i = 0; i < 8; i++) {
            int lin = tid + NTHR * i;
            int e = lin >> 5, kk = lin & 31;
            float v;
            if (seg == 0)      v = x[(size_t)sIdx[e]      * DD + koff + kk];
            else if (seg == 1) v = x[(size_t)sIdx[64 + e] * DD + koff + kk];
            else               v = (e < Eloc) ? ea[(size_t)(eb + e) * DD + koff + kk] : 0.f;
            Es[e * 33 + kk] = v;
        }
        const float4* Wg  = (const float4*)(W1 + (size_t)k0 * DD);
        float4*       Ws4 = (float4*)Ws;
#pragma unroll
        for (int i = 0; i < 4; i++) Ws4[tid + NTHR * i] = Wg[tid + NTHR * i];
        __syncthreads();
#pragma unroll
        for (int kk = 0; kk < 32; kk++) {
            float av[4];
            av[0] = Es[(m0 + 0) * 33 + kk];
            av[1] = Es[(m0 + 1) * 33 + kk];
            av[2] = Es[(m0 + 2) * 33 + kk];
            av[3] = Es[(m0 + 3) * 33 + kk];
            const float* wr = Ws + kk * DD + n0;
            float4 w0 = *(const float4*)wr;
            float4 w1 = *(const float4*)(wr + 4);
            float wv[8] = {w0.x, w0.y, w0.z, w0.w, w1.x, w1.y, w1.z, w1.w};
#pragma unroll
            for (int i = 0; i < 4; i++)
#pragma unroll
                for (int j = 0; j < 8; j++) acc[i][j] += av[i] * wv[j];
        }
        __syncthreads();
    }

    // bias + relu -> Hs
    {
        float bb[8];
#pragma unroll
        for (int j = 0; j < 8; j++) bb[j] = b1[n0 + j];
#pragma unroll
        for (int i = 0; i < 4; i++) {
#pragma unroll
            for (int j = 0; j < 8; j++) {
                float v = acc[i][j] + bb[j];
                acc[i][j] = v > 0.f ? v : 0.f;
            }
            float4 v0 = make_float4(acc[i][0], acc[i][1], acc[i][2], acc[i][3]);
            float4 v1 = make_float4(acc[i][4], acc[i][5], acc[i][6], acc[i][7]);
            *(float4*)&Hs[(m0 + i) * 132 + n0]     = v0;
            *(float4*)&Hs[(m0 + i) * 132 + n0 + 4] = v1;
        }
    }
    __syncthreads();

    // ---- GEMM2: [64 x 128] @ [128 x 128], 4 k-chunks ----
#pragma unroll
    for (int i = 0; i < 4; i++)
#pragma unroll
        for (int j = 0; j < 8; j++) acc[i][j] = 0.f;
#pragma unroll 1
    for (int kc = 0; kc < 4; kc++) {
        const int k0 = kc * 32;
        const float4* Wg  = (const float4*)(W2 + (size_t)k0 * DD);
        float4*       Ws4 = (float4*)Ws;
#pragma unroll
        for (int i = 0; i < 4; i++) Ws4[tid + NTHR * i] = Wg[tid + NTHR * i];
        __syncthreads();
#pragma unroll
        for (int kk = 0; kk < 32; kk++) {
            int k = k0 + kk;
            float av[4];
            av[0] = Hs[(m0 + 0) * 132 + k];
            av[1] = Hs[(m0 + 1) * 132 + k];
            av[2] = Hs[(m0 + 2) * 132 + k];
            av[3] = Hs[(m0 + 3) * 132 + k];
            const float* wr = Ws + kk * DD + n0;
            float4 w0 = *(const float4*)wr;
            float4 w1 = *(const float4*)(wr + 4);
            float wv[8] = {w0.x, w0.y, w0.z, w0.w, w1.x, w1.y, w1.z, w1.w};
#pragma unroll
            for (int i = 0; i < 4; i++)
#pragma unroll
                for (int j = 0; j < 8; j++) acc[i][j] += av[i] * wv[j];
        }
        __syncthreads();
    }
    // bias -> Hs (pre-LN)
    {
        float bb[8];
#pragma unroll
        for (int j = 0; j < 8; j++) bb[j] = b2[n0 + j];
#pragma unroll
        for (int i = 0; i < 4; i++) {
            float4 v0 = make_float4(acc[i][0] + bb[0], acc[i][1] + bb[1], acc[i][2] + bb[2], acc[i][3] + bb[3]);
            float4 v1 = make_float4(acc[i][4] + bb[4], acc[i][5] + bb[5], acc[i][6] + bb[6], acc[i][7] + bb[7]);
            *(float4*)&Hs[(m0 + i) * 132 + n0]     = v0;
            *(float4*)&Hs[(m0 + i) * 132 + n0 + 4] = v1;
        }
    }
    __syncthreads();

    // ---- LayerNorm + residual + scatter (warp per row-group) ----
    const int wid = tid >> 5, lane = tid & 31;
#pragma unroll 1
    for (int j = 0; j < 8; j++) {
        int r = wid * 8 + j;            // warp-uniform
        if (r >= Eloc) continue;
        size_t ge = (size_t)(eb + r);
        float v[4], s = 0.f, sq = 0.f;
#pragma unroll
        for (int q = 0; q < 4; q++) {
            v[q] = Hs[r * 132 + lane + 32 * q];
            s += v[q]; sq += v[q] * v[q];
        }
        warp_red2(s, sq);
        float mu  = s * (1.f / 128.f);
        float var = sq * (1.f / 128.f) - mu * mu;
        float inv = rsqrtf(var + 1e-5f);
        size_t dn = (size_t)sIdx[64 + r];
#pragma unroll
        for (int q = 0; q < 4; q++) {
            int c = lane + 32 * q;
            float o = (v[q] - mu) * inv * gma[c] + bta[c];
            eout[ge * DD + c] = ea[ge * DD + c] + o;
            atomicAdd(&g_agg[dn * DD + c], o);
        }
    }
}

// ---------------------------------------------------------------------------
// Node kernel: n_in = [x, agg] (256) -> MLP -> LN -> x_pre = x + h
// Also accumulates per-column sums and total sum-of-squares for PairNorm.
// ---------------------------------------------------------------------------
__global__ void node_kernel(const float* __restrict__ x,
                            const float* __restrict__ W1, const float* __restrict__ b1,
                            const float* __restrict__ W2, const float* __restrict__ b2,
                            const float* __restrict__ gma, const float* __restrict__ bta,
                            float* __restrict__ xpre, int Nn)
{
    extern __shared__ float sm[];
    float* Es = sm + ES_OFF;
    float* Ws = sm + WS_OFF;
    float* Hs = sm + HS_OFF;
    float* csum_s = sm + TL_OFF;   // 128 col sums + [128] = sumsq

    const int tid  = threadIdx.x;
    const int nb   = blockIdx.x * TM;
    const int Nloc = min(TM, Nn - nb);

    if (tid < 129) csum_s[tid] = 0.f;

    const int tm = tid >> 4, tn = tid & 15;
    const int m0 = tm * 4,  n0 = tn * 8;

    float acc[4][8];
#pragma unroll
    for (int i = 0; i < 4; i++)
#pragma unroll
        for (int j = 0; j < 8; j++) acc[i][j] = 0.f;

    // ---- GEMM1: [64 x 256] @ [256 x 128], 8 k-chunks ----
#pragma unroll 1
    for (int kc = 0; kc < 8; kc++) {
        const int k0   = kc * 32;
        const int seg  = k0 >> 7;    // 0: x, 1: agg
        const int koff = k0 & 127;
#pragma unroll
        for (int i = 0; i < 8; i++) {
            int lin = tid + NTHR * i;
            int e = lin >> 5, kk = lin & 31;
            float v = 0.f;
            if (e < Nloc) {
                size_t row = (size_t)(nb + e);
                v = (seg == 0) ? x[row * DD + koff + kk]
                               : g_agg[row * DD + koff + kk];
            }
            Es[e * 33 + kk] = v;
        }
        const float4* Wg  = (const float4*)(W1 + (size_t)k0 * DD);
        float4*       Ws4 = (float4*)Ws;
#pragma unroll
        for (int i = 0; i < 4; i++) Ws4[tid + NTHR * i] = Wg[tid + NTHR * i];
        __syncthreads();
#pragma unroll
        for (int kk = 0; kk < 32; kk++) {
            float av[4];
            av[0] = Es[(m0 + 0) * 33 + kk];
            av[1] = Es[(m0 + 1) * 33 + kk];
            av[2] = Es[(m0 + 2) * 33 + kk];
            av[3] = Es[(m0 + 3) * 33 + kk];
            const float* wr = Ws + kk * DD + n0;
            float4 w0 = *(const float4*)wr;
            float4 w1 = *(const float4*)(wr + 4);
            float wv[8] = {w0.x, w0.y, w0.z, w0.w, w1.x, w1.y, w1.z, w1.w};
#pragma unroll
            for (int i = 0; i < 4; i++)
#pragma unroll
                for (int j = 0; j < 8; j++) acc[i][j] += av[i] * wv[j];
        }
        __syncthreads();
    }

    {
        float bb[8];
#pragma unroll
        for (int j = 0; j < 8; j++) bb[j] = b1[n0 + j];
#pragma unroll
        for (int i = 0; i < 4; i++) {
#pragma unroll
            for (int j = 0; j < 8; j++) {
                float v = acc[i][j] + bb[j];
                acc[i][j] = v > 0.f ? v : 0.f;
            }
            float4 v0 = make_float4(acc[i][0], acc[i][1], acc[i][2], acc[i][3]);
            float4 v1 = make_float4(acc[i][4], acc[i][5], acc[i][6], acc[i][7]);
            *(float4*)&Hs[(m0 + i) * 132 + n0]     = v0;
            *(float4*)&Hs[(m0 + i) * 132 + n0 + 4] = v1;
        }
    }
    __syncthreads();

    // ---- GEMM2 ----
#pragma unroll
    for (int i = 0; i < 4; i++)
#pragma unroll
        for (int j = 0; j < 8; j++) acc[i][j] = 0.f;
#pragma unroll 1
    for (int kc = 0; kc < 4; kc++) {
        const int k0 = kc * 32;
        const float4* Wg  = (const float4*)(W2 + (size_t)k0 * DD);
        float4*       Ws4 = (float4*)Ws;
#pragma unroll
        for (int i = 0; i < 4; i++) Ws4[tid + NTHR * i] = Wg[tid + NTHR * i];
        __syncthreads();
#pragma unroll
        for (int kk = 0; kk < 32; kk++) {
            int k = k0 + kk;
            float av[4];
            av[0] = Hs[(m0 + 0) * 132 + k];
            av[1] = Hs[(m0 + 1) * 132 + k];
            av[2] = Hs[(m0 + 2) * 132 + k];
            av[3] = Hs[(m0 + 3) * 132 + k];
            const float* wr = Ws + kk * DD + n0;
            float4 w0 = *(const float4*)wr;
            float4 w1 = *(const float4*)(wr + 4);
            float wv[8] = {w0.x, w0.y, w0.z, w0.w, w1.x, w1.y, w1.z, w1.w};
#pragma unroll
            for (int i = 0; i < 4; i++)
#pragma unroll
                for (int j = 0; j < 8; j++) acc[i][j] += av[i] * wv[j];
        }
        __syncthreads();
    }
    {
        float bb[8];
#pragma unroll
        for (int j = 0; j < 8; j++) bb[j] = b2[n0 + j];
#pragma unroll
        for (int i = 0; i < 4; i++) {
            float4 v0 = make_float4(acc[i][0] + bb[0], acc[i][1] + bb[1], acc[i][2] + bb[2], acc[i][3] + bb[3]);
            float4 v1 = make_float4(acc[i][4] + bb[4], acc[i][5] + bb[5], acc[i][6] + bb[6], acc[i][7] + bb[7]);
            *(float4*)&Hs[(m0 + i) * 132 + n0]     = v0;
            *(float4*)&Hs[(m0 + i) * 132 + n0 + 4] = v1;
        }
    }
    __syncthreads();

    // ---- LN + residual + PairNorm partial reductions ----
    const int wid = tid >> 5, lane = tid & 31;
    float csum[4] = {0.f, 0.f, 0.f, 0.f};
    float sq_acc = 0.f;
#pragma unroll 1
    for (int j = 0; j < 8; j++) {
        int r = wid * 8 + j;            // warp-uniform
        if (r >= Nloc) continue;
        size_t gn = (size_t)(nb + r);
        float v[4], s = 0.f, sq = 0.f;
#pragma unroll
        for (int q = 0; q < 4; q++) {
            v[q] = Hs[r * 132 + lane + 32 * q];
            s += v[q]; sq += v[q] * v[q];
        }
        warp_red2(s, sq);
        float mu  = s * (1.f / 128.f);
        float var = sq * (1.f / 128.f) - mu * mu;
        float inv = rsqrtf(var + 1e-5f);
#pragma unroll
        for (int q = 0; q < 4; q++) {
            int c = lane + 32 * q;
            float o  = (v[q] - mu) * inv * gma[c] + bta[c];
            float xp = x[gn * DD + c] + o;
            xpre[gn * DD + c] = xp;
            csum[q] += xp;
            sq_acc  += xp * xp;
        }
    }
#pragma unroll
    for (int q = 0; q < 4; q++) atomicAdd(&csum_s[lane + 32 * q], csum[q]);
#pragma unroll
    for (int o = 16; o > 0; o >>= 1) sq_acc += __shfl_xor_sync(0xffffffffu, sq_acc, o);
    if (lane == 0) atomicAdd(&csum_s[128], sq_acc);
    __syncthreads();
    if (tid < 128)       atomicAdd(&g_colsum[tid], csum_s[tid]);
    else if (tid == 128) atomicAdd(&g_sumsq[0],    csum_s[128]);
}

// ---------------------------------------------------------------------------
__global__ void rms_kernel(int Nn)
{
    __shared__ float red[128];
    int c = threadIdx.x;
    float m = g_colsum[c] / (float)Nn;
    g_mean[c] = m;
    red[c] = m * m;
    __syncthreads();
    for (int o = 64; o > 0; o >>= 1) {
        if (c < o) red[c] += red[c + o];
        __syncthreads();
    }
    if (c == 0) {
        float ssc = g_sumsq[0] - (float)Nn * red[0];
        float rms = sqrtf(ssc / (float)Nn) + 1e-8f;
        g_invrms[0] = 1.0f / rms;
    }
}

__global__ void finalize_kernel(float* __restrict__ xout, int total)
{
    int idx = blockIdx.x * blockDim.x + threadIdx.x;
    if (idx < total) {
        int c = idx & 127;
        xout[idx] = (xout[idx] - g_mean[c]) * g_invrms[0];
    }
}

// ---------------------------------------------------------------------------
extern "C" void kernel_launch(void* const* d_in, const int* in_sizes, int n_in,
                              void* d_out, int out_size)
{
    const float* x   = (const float*)d_in[0];
    const float* ea  = (const float*)d_in[1];
    const int*   ei  = (const int*)d_in[2];      // edge_index: int32 (JAX x64 disabled)
    const float* eW1 = (const float*)d_in[3];
    const float* eb1 = (const float*)d_in[4];
    const float* eW2 = (const float*)d_in[5];
    const float* eb2 = (const float*)d_in[6];
    const float* eg  = (const float*)d_in[7];
    const float* ebt = (const float*)d_in[8];
    const float* nW1 = (const float*)d_in[9];
    const float* nb1 = (const float*)d_in[10];
    const float* nW2 = (const float*)d_in[11];
    const float* nb2 = (const float*)d_in[12];
    const float* ng  = (const float*)d_in[13];
    const float* nbt = (const float*)d_in[14];

    const int Nn = in_sizes[0] / DD;
    const int E  = in_sizes[1] / DD;

    float* xout = (float*)d_out;              // [Nn * D]
    float* eout = xout + (size_t)Nn * DD;     // [E * D]

    cudaFuncSetAttribute(edge_kernel, cudaFuncAttributeMaxDynamicSharedMemorySize, SMEM_BYTES);
    cudaFuncSetAttribute(node_kernel, cudaFuncAttributeMaxDynamicSharedMemorySize, SMEM_BYTES);

    void *aggp, *csp, *sqp;
    cudaGetSymbolAddress(&aggp, g_agg);
    cudaGetSymbolAddress(&csp,  g_colsum);
    cudaGetSymbolAddress(&sqp,  g_sumsq);
    cudaMemsetAsync(aggp, 0, (size_t)Nn * DD * sizeof(float));
    cudaMemsetAsync(csp,  0, DD * sizeof(float));
    cudaMemsetAsync(sqp,  0, sizeof(float));

    const int eblocks = (E + TM - 1) / TM;
    edge_kernel<<<eblocks, NTHR, SMEM_BYTES>>>(x, ea, ei, eW1, eb1, eW2, eb2, eg, ebt, eout, E);

    const int nblocks = (Nn + TM - 1) / TM;
    node_kernel<<<nblocks, NTHR, SMEM_BYTES>>>(x, nW1, nb1, nW2, nb2, ng, nbt, xout, Nn);

    rms_kernel<<<1, 128>>>(Nn);

    const int total = Nn * DD;
    finalize_kernel<<<(total + 255) / 256, 256>>>(xout, total);
}

// round 4
// speedup vs baseline: 2.1020x; 2.1020x over previous
#include <cuda_runtime.h>
#include <cuda_bf16.h>

#define DD   128
#define EB   128          // rows (edges/nodes) per block
#define NTHR 256
#define MAXN 100000

#define STA  136          // bf16 element stride of A/B smem tiles (row pad 8)
#define STH  132          // float stride of output tile

// dynamic smem byte offsets
#define OFF_AH   0
#define OFF_AL   34816
#define OFF_BH   69632
#define OFF_BL   104448
#define OFF_TAIL 139264
#define SMEM_BYTES 140800

// Scratch (device globals — no runtime allocation allowed)
__device__ float g_agg[(size_t)MAXN * DD];
__device__ float g_colsum[DD];
__device__ float g_sumsq[1];
__device__ float g_mean[DD];
__device__ float g_invrms[1];

static __device__ __forceinline__ void warp_red2(float& a, float& b) {
#pragma unroll
    for (int o = 16; o > 0; o >>= 1) {
        a += __shfl_xor_sync(0xffffffffu, a, o);
        b += __shfl_xor_sync(0xffffffffu, b, o);
    }
}

static __device__ __forceinline__ void ldsm4(unsigned r[4], unsigned addr) {
    asm volatile("ldmatrix.sync.aligned.m8n8.x4.shared.b16 {%0,%1,%2,%3}, [%4];\n"
                 : "=r"(r[0]), "=r"(r[1]), "=r"(r[2]), "=r"(r[3]) : "r"(addr));
}
static __device__ __forceinline__ void ldsm4t(unsigned r[4], unsigned addr) {
    asm volatile("ldmatrix.sync.aligned.m8n8.x4.trans.shared.b16 {%0,%1,%2,%3}, [%4];\n"
                 : "=r"(r[0]), "=r"(r[1]), "=r"(r[2]), "=r"(r[3]) : "r"(addr));
}
static __device__ __forceinline__ void mma16816(float d[4], const unsigned a[4],
                                                unsigned b0, unsigned b1) {
    asm volatile("mma.sync.aligned.m16n8k16.row.col.f32.bf16.bf16.f32 "
                 "{%0,%1,%2,%3}, {%4,%5,%6,%7}, {%8,%9}, {%0,%1,%2,%3};\n"
                 : "+f"(d[0]), "+f"(d[1]), "+f"(d[2]), "+f"(d[3])
                 : "r"(a[0]), "r"(a[1]), "r"(a[2]), "r"(a[3]), "r"(b0), "r"(b1));
}

// split fp32 float4 -> (hi, lo) bf16 and store 4 elems at [r][c]
static __device__ __forceinline__ void split_store(__nv_bfloat16* H, __nv_bfloat16* L,
                                                   int r, int c, float4 v) {
    __nv_bfloat162 h01 = __floats2bfloat162_rn(v.x, v.y);
    __nv_bfloat162 h23 = __floats2bfloat162_rn(v.z, v.w);
    __nv_bfloat162 l01 = __floats2bfloat162_rn(v.x - __bfloat162float(h01.x),
                                               v.y - __bfloat162float(h01.y));
    __nv_bfloat162 l23 = __floats2bfloat162_rn(v.z - __bfloat162float(h23.x),
                                               v.w - __bfloat162float(h23.y));
    *(__nv_bfloat162*)(H + r * STA + c)     = h01;
    *(__nv_bfloat162*)(H + r * STA + c + 2) = h23;
    *(__nv_bfloat162*)(L + r * STA + c)     = l01;
    *(__nv_bfloat162*)(L + r * STA + c + 2) = l23;
}

// one K=128 chunk of 3-pass bf16-split MMA: acc += A(128xK) * B(KxN=128)
static __device__ __forceinline__ void mma_chunk(float acc[2][8][4],
                                                 unsigned ah_b, unsigned al_b,
                                                 unsigned bh_b, unsigned bl_b,
                                                 int wm, int wn, int lane) {
    const int ar  = (lane & 15);
    const int asl = (lane >> 4) * 8;
#pragma unroll 1
    for (int ks = 0; ks < 8; ks++) {
        unsigned a_h[2][4], a_l[2][4];
        const int acol = ks * 16 + asl;
#pragma unroll
        for (int mt = 0; mt < 2; mt++) {
            int arow = wm * 32 + mt * 16 + ar;
            unsigned off = (unsigned)((arow * STA + acol) * 2);
            ldsm4(a_h[mt], ah_b + off);
            ldsm4(a_l[mt], al_b + off);
        }
        const int brow = ks * 16 + ar;
#pragma unroll
        for (int np = 0; np < 4; np++) {
            int bcol = wn * 64 + np * 16 + asl;
            unsigned off = (unsigned)((brow * STA + bcol) * 2);
            unsigned bh[4], bl[4];
            ldsm4t(bh, bh_b + off);
            ldsm4t(bl, bl_b + off);
#pragma unroll
            for (int mt = 0; mt < 2; mt++) {
                mma16816(acc[mt][2 * np],     a_h[mt], bh[0], bh[1]);
                mma16816(acc[mt][2 * np],     a_h[mt], bl[0], bl[1]);
                mma16816(acc[mt][2 * np],     a_l[mt], bh[0], bh[1]);
                mma16816(acc[mt][2 * np + 1], a_h[mt], bh[2], bh[3]);
                mma16816(acc[mt][2 * np + 1], a_h[mt], bl[2], bl[3]);
                mma16816(acc[mt][2 * np + 1], a_l[mt], bh[2], bh[3]);
            }
        }
    }
}

static __device__ __forceinline__ void load_w_chunk(const float* __restrict__ W, int k0,
                                                    __nv_bfloat16* Bh, __nv_bfloat16* Bl,
                                                    int tid) {
#pragma unroll
    for (int i = 0; i < 16; i++) {
        int idx = tid + NTHR * i;
        int k = idx >> 5, c = (idx & 31) * 4;
        float4 v = *(const float4*)(W + (size_t)(k0 + k) * DD + c);
        split_store(Bh, Bl, k, c, v);
    }
}

// ---------------------------------------------------------------------------
__global__ __launch_bounds__(NTHR)
void edge_kernel(const float* __restrict__ x,
                 const float* __restrict__ ea,
                 const int* __restrict__ ei,
                 const float* __restrict__ W1, const float* __restrict__ b1,
                 const float* __restrict__ W2, const float* __restrict__ b2,
                 const float* __restrict__ gma, const float* __restrict__ bta,
                 float* __restrict__ eout, int E)
{
    extern __shared__ char smc[];
    __nv_bfloat16* Ah = (__nv_bfloat16*)(smc + OFF_AH);
    __nv_bfloat16* Al = (__nv_bfloat16*)(smc + OFF_AL);
    __nv_bfloat16* Bh = (__nv_bfloat16*)(smc + OFF_BH);
    __nv_bfloat16* Bl = (__nv_bfloat16*)(smc + OFF_BL);
    float*         Hs = (float*)(smc + OFF_AH);          // aliases Ah/Al (phase-disjoint)
    int*         sIdx = (int*)(smc + OFF_TAIL);          // [0..127]=src, [128..255]=dst

    const int tid = threadIdx.x, lane = tid & 31, wid = tid >> 5;
    const int wm = wid & 3, wn = wid >> 2;
    const int eb = blockIdx.x * EB;
    const int Eloc = min(EB, E - eb);

    if (tid < 128) sIdx[tid] = (tid < Eloc) ? ei[eb + tid] : 0;
    else { int t2 = tid - 128; sIdx[tid] = (t2 < Eloc) ? ei[E + eb + t2] : 0; }
    __syncthreads();

    const unsigned ah_b = (unsigned)__cvta_generic_to_shared(Ah);
    const unsigned al_b = (unsigned)__cvta_generic_to_shared(Al);
    const unsigned bh_b = (unsigned)__cvta_generic_to_shared(Bh);
    const unsigned bl_b = (unsigned)__cvta_generic_to_shared(Bl);

    float acc[2][8][4];
#pragma unroll
    for (int mt = 0; mt < 2; mt++)
#pragma unroll
        for (int nt = 0; nt < 8; nt++)
#pragma unroll
            for (int q = 0; q < 4; q++) acc[mt][nt][q] = 0.f;

    // ---- GEMM1: K=384 in 3 chunks of 128 (x[src], x[dst], edge_attr) ----
#pragma unroll 1
    for (int seg = 0; seg < 3; seg++) {
#pragma unroll
        for (int i = 0; i < 16; i++) {
            int idx = tid + NTHR * i;
            int r = idx >> 5, c = (idx & 31) * 4;
            float4 v;
            if (seg == 0)      v = *(const float4*)(x + (size_t)sIdx[r] * DD + c);
            else if (seg == 1) v = *(const float4*)(x + (size_t)sIdx[128 + r] * DD + c);
            else if (r < Eloc) v = *(const float4*)(ea + (size_t)(eb + r) * DD + c);
            else               v = make_float4(0.f, 0.f, 0.f, 0.f);
            split_store(Ah, Al, r, c, v);
        }
        load_w_chunk(W1, seg * DD, Bh, Bl, tid);
        __syncthreads();
        mma_chunk(acc, ah_b, al_b, bh_b, bl_b, wm, wn, lane);
        __syncthreads();
    }

    // ---- bias + relu, hidden -> Ah/Al (split bf16); zero acc ----
    {
        const int g = lane >> 2, t = lane & 3;
#pragma unroll
        for (int mt = 0; mt < 2; mt++) {
#pragma unroll
            for (int nt = 0; nt < 8; nt++) {
                int col = wn * 64 + nt * 8 + t * 2;
                float bx = b1[col], by = b1[col + 1];
                int r0 = wm * 32 + mt * 16 + g;
                float h0 = fmaxf(acc[mt][nt][0] + bx, 0.f);
                float h1 = fmaxf(acc[mt][nt][1] + by, 0.f);
                float h2 = fmaxf(acc[mt][nt][2] + bx, 0.f);
                float h3 = fmaxf(acc[mt][nt][3] + by, 0.f);
                __nv_bfloat162 hh0 = __floats2bfloat162_rn(h0, h1);
                __nv_bfloat162 ll0 = __floats2bfloat162_rn(h0 - __bfloat162float(hh0.x),
                                                           h1 - __bfloat162float(hh0.y));
                *(__nv_bfloat162*)(Ah + r0 * STA + col) = hh0;
                *(__nv_bfloat162*)(Al + r0 * STA + col) = ll0;
                __nv_bfloat162 hh1 = __floats2bfloat162_rn(h2, h3);
                __nv_bfloat162 ll1 = __floats2bfloat162_rn(h2 - __bfloat162float(hh1.x),
                                                           h3 - __bfloat162float(hh1.y));
                *(__nv_bfloat162*)(Ah + (r0 + 8) * STA + col) = hh1;
                *(__nv_bfloat162*)(Al + (r0 + 8) * STA + col) = ll1;
                acc[mt][nt][0] = acc[mt][nt][1] = acc[mt][nt][2] = acc[mt][nt][3] = 0.f;
            }
        }
    }
    load_w_chunk(W2, 0, Bh, Bl, tid);
    __syncthreads();
    mma_chunk(acc, ah_b, al_b, bh_b, bl_b, wm, wn, lane);
    __syncthreads();

    // ---- +b2 -> Hs (pre-LN) ----
    {
        const int g = lane >> 2, t = lane & 3;
#pragma unroll
        for (int mt = 0; mt < 2; mt++) {
#pragma unroll
            for (int nt = 0; nt < 8; nt++) {
                int col = wn * 64 + nt * 8 + t * 2;
                float bx = b2[col], by = b2[col + 1];
                int r0 = wm * 32 + mt * 16 + g;
                *(float2*)(Hs + r0 * STH + col)       = make_float2(acc[mt][nt][0] + bx, acc[mt][nt][1] + by);
                *(float2*)(Hs + (r0 + 8) * STH + col) = make_float2(acc[mt][nt][2] + bx, acc[mt][nt][3] + by);
            }
        }
    }
    __syncthreads();

    // ---- LN + edge residual + scatter-add (16 rows per warp) ----
#pragma unroll 1
    for (int j = 0; j < 16; j++) {
        int r = wid * 16 + j;            // warp-uniform
        if (r >= Eloc) continue;
        size_t ge = (size_t)(eb + r);
        float v[4], s = 0.f, sq = 0.f;
#pragma unroll
        for (int q = 0; q < 4; q++) {
            v[q] = Hs[r * STH + lane + 32 * q];
            s += v[q]; sq += v[q] * v[q];
        }
        warp_red2(s, sq);
        float mu  = s * (1.f / 128.f);
        float var = sq * (1.f / 128.f) - mu * mu;
        float inv = rsqrtf(var + 1e-5f);
        size_t dn = (size_t)sIdx[128 + r];
#pragma unroll
        for (int q = 0; q < 4; q++) {
            int c = lane + 32 * q;
            float o = (v[q] - mu) * inv * gma[c] + bta[c];
            eout[ge * DD + c] = ea[ge * DD + c] + o;
            atomicAdd(&g_agg[dn * DD + c], o);
        }
    }
}

// ---------------------------------------------------------------------------
__global__ __launch_bounds__(NTHR)
void node_kernel(const float* __restrict__ x,
                 const float* __restrict__ W1, const float* __restrict__ b1,
                 const float* __restrict__ W2, const float* __restrict__ b2,
                 const float* __restrict__ gma, const float* __restrict__ bta,
                 float* __restrict__ xpre, int Nn)
{
    extern __shared__ char smc[];
    __nv_bfloat16* Ah = (__nv_bfloat16*)(smc + OFF_AH);
    __nv_bfloat16* Al = (__nv_bfloat16*)(smc + OFF_AL);
    __nv_bfloat16* Bh = (__nv_bfloat16*)(smc + OFF_BH);
    __nv_bfloat16* Bl = (__nv_bfloat16*)(smc + OFF_BL);
    float*         Hs = (float*)(smc + OFF_AH);
    float*     csum_s = (float*)(smc + OFF_TAIL);        // 128 col sums + [128]=sumsq

    const int tid = threadIdx.x, lane = tid & 31, wid = tid >> 5;
    const int wm = wid & 3, wn = wid >> 2;
    const int nb = blockIdx.x * EB;
    const int Nloc = min(EB, Nn - nb);

    if (tid < 129) csum_s[tid] = 0.f;

    const unsigned ah_b = (unsigned)__cvta_generic_to_shared(Ah);
    const unsigned al_b = (unsigned)__cvta_generic_to_shared(Al);
    const unsigned bh_b = (unsigned)__cvta_generic_to_shared(Bh);
    const unsigned bl_b = (unsigned)__cvta_generic_to_shared(Bl);

    float acc[2][8][4];
#pragma unroll
    for (int mt = 0; mt < 2; mt++)
#pragma unroll
        for (int nt = 0; nt < 8; nt++)
#pragma unroll
            for (int q = 0; q < 4; q++) acc[mt][nt][q] = 0.f;

    // ---- GEMM1: K=256 in 2 chunks (x, agg) ----
#pragma unroll 1
    for (int seg = 0; seg < 2; seg++) {
#pragma unroll
        for (int i = 0; i < 16; i++) {
            int idx = tid + NTHR * i;
            int r = idx >> 5, c = (idx & 31) * 4;
            float4 v = make_float4(0.f, 0.f, 0.f, 0.f);
            if (r < Nloc) {
                size_t row = (size_t)(nb + r);
                v = (seg == 0) ? *(const float4*)(x + row * DD + c)
                               : *(const float4*)(g_agg + row * DD + c);
            }
            split_store(Ah, Al, r, c, v);
        }
        load_w_chunk(W1, seg * DD, Bh, Bl, tid);
        __syncthreads();
        mma_chunk(acc, ah_b, al_b, bh_b, bl_b, wm, wn, lane);
        __syncthreads();
    }

    // ---- bias + relu -> hidden ----
    {
        const int g = lane >> 2, t = lane & 3;
#pragma unroll
        for (int mt = 0; mt < 2; mt++) {
#pragma unroll
            for (int nt = 0; nt < 8; nt++) {
                int col = wn * 64 + nt * 8 + t * 2;
                float bx = b1[col], by = b1[col + 1];
                int r0 = wm * 32 + mt * 16 + g;
                float h0 = fmaxf(acc[mt][nt][0] + bx, 0.f);
                float h1 = fmaxf(acc[mt][nt][1] + by, 0.f);
                float h2 = fmaxf(acc[mt][nt][2] + bx, 0.f);
                float h3 = fmaxf(acc[mt][nt][3] + by, 0.f);
                __nv_bfloat162 hh0 = __floats2bfloat162_rn(h0, h1);
                __nv_bfloat162 ll0 = __floats2bfloat162_rn(h0 - __bfloat162float(hh0.x),
                                                           h1 - __bfloat162float(hh0.y));
                *(__nv_bfloat162*)(Ah + r0 * STA + col) = hh0;
                *(__nv_bfloat162*)(Al + r0 * STA + col) = ll0;
                __nv_bfloat162 hh1 = __floats2bfloat162_rn(h2, h3);
                __nv_bfloat162 ll1 = __floats2bfloat162_rn(h2 - __bfloat162float(hh1.x),
                                                           h3 - __bfloat162float(hh1.y));
                *(__nv_bfloat162*)(Ah + (r0 + 8) * STA + col) = hh1;
                *(__nv_bfloat162*)(Al + (r0 + 8) * STA + col) = ll1;
                acc[mt][nt][0] = acc[mt][nt][1] = acc[mt][nt][2] = acc[mt][nt][3] = 0.f;
            }
        }
    }
    load_w_chunk(W2, 0, Bh, Bl, tid);
    __syncthreads();
    mma_chunk(acc, ah_b, al_b, bh_b, bl_b, wm, wn, lane);
    __syncthreads();

    {
        const int g = lane >> 2, t = lane & 3;
#pragma unroll
        for (int mt = 0; mt < 2; mt++) {
#pragma unroll
            for (int nt = 0; nt < 8; nt++) {
                int col = wn * 64 + nt * 8 + t * 2;
                float bx = b2[col], by = b2[col + 1];
                int r0 = wm * 32 + mt * 16 + g;
                *(float2*)(Hs + r0 * STH + col)       = make_float2(acc[mt][nt][0] + bx, acc[mt][nt][1] + by);
                *(float2*)(Hs + (r0 + 8) * STH + col) = make_float2(acc[mt][nt][2] + bx, acc[mt][nt][3] + by);
            }
        }
    }
    __syncthreads();

    // ---- LN + residual + PairNorm partials ----
    float csum[4] = {0.f, 0.f, 0.f, 0.f};
    float sq_acc = 0.f;
#pragma unroll 1
    for (int j = 0; j < 16; j++) {
        int r = wid * 16 + j;
        if (r >= Nloc) continue;
        size_t gn = (size_t)(nb + r);
        float v[4], s = 0.f, sq = 0.f;
#pragma unroll
        for (int q = 0; q < 4; q++) {
            v[q] = Hs[r * STH + lane + 32 * q];
            s += v[q]; sq += v[q] * v[q];
        }
        warp_red2(s, sq);
        float mu  = s * (1.f / 128.f);
        float var = sq * (1.f / 128.f) - mu * mu;
        float inv = rsqrtf(var + 1e-5f);
#pragma unroll
        for (int q = 0; q < 4; q++) {
            int c = lane + 32 * q;
            float o  = (v[q] - mu) * inv * gma[c] + bta[c];
            float xp = x[gn * DD + c] + o;
            xpre[gn * DD + c] = xp;
            csum[q] += xp;
            sq_acc  += xp * xp;
        }
    }
#pragma unroll
    for (int q = 0; q < 4; q++) atomicAdd(&csum_s[lane + 32 * q], csum[q]);
#pragma unroll
    for (int o = 16; o > 0; o >>= 1) sq_acc += __shfl_xor_sync(0xffffffffu, sq_acc, o);
    if (lane == 0) atomicAdd(&csum_s[128], sq_acc);
    __syncthreads();
    if (tid < 128)       atomicAdd(&g_colsum[tid], csum_s[tid]);
    else if (tid == 128) atomicAdd(&g_sumsq[0],    csum_s[128]);
}

// ---------------------------------------------------------------------------
__global__ void rms_kernel(int Nn)
{
    __shared__ float red[128];
    int c = threadIdx.x;
    float m = g_colsum[c] / (float)Nn;
    g_mean[c] = m;
    red[c] = m * m;
    __syncthreads();
    for (int o = 64; o > 0; o >>= 1) {
        if (c < o) red[c] += red[c + o];
        __syncthreads();
    }
    if (c == 0) {
        float ssc = g_sumsq[0] - (float)Nn * red[0];
        float rms = sqrtf(ssc / (float)Nn) + 1e-8f;
        g_invrms[0] = 1.0f / rms;
    }
}

__global__ void finalize_kernel(float* __restrict__ xout, int total)
{
    int idx = blockIdx.x * blockDim.x + threadIdx.x;
    if (idx < total) {
        int c = idx & 127;
        xout[idx] = (xout[idx] - g_mean[c]) * g_invrms[0];
    }
}

// ---------------------------------------------------------------------------
extern "C" void kernel_launch(void* const* d_in, const int* in_sizes, int n_in,
                              void* d_out, int out_size)
{
    const float* x   = (const float*)d_in[0];
    const float* ea  = (const float*)d_in[1];
    const int*   ei  = (const int*)d_in[2];      // edge_index: int32 (JAX x64 disabled)
    const float* eW1 = (const float*)d_in[3];
    const float* eb1 = (const float*)d_in[4];
    const float* eW2 = (const float*)d_in[5];
    const float* eb2 = (const float*)d_in[6];
    const float* eg  = (const float*)d_in[7];
    const float* ebt = (const float*)d_in[8];
    const float* nW1 = (const float*)d_in[9];
    const float* nb1 = (const float*)d_in[10];
    const float* nW2 = (const float*)d_in[11];
    const float* nb2 = (const float*)d_in[12];
    const float* ng  = (const float*)d_in[13];
    const float* nbt = (const float*)d_in[14];

    const int Nn = in_sizes[0] / DD;
    const int E  = in_sizes[1] / DD;

    float* xout = (float*)d_out;              // [Nn * D]
    float* eout = xout + (size_t)Nn * DD;     // [E * D]

    cudaFuncSetAttribute(edge_kernel, cudaFuncAttributeMaxDynamicSharedMemorySize, SMEM_BYTES);
    cudaFuncSetAttribute(node_kernel, cudaFuncAttributeMaxDynamicSharedMemorySize, SMEM_BYTES);

    void *aggp, *csp, *sqp;
    cudaGetSymbolAddress(&aggp, g_agg);
    cudaGetSymbolAddress(&csp,  g_colsum);
    cudaGetSymbolAddress(&sqp,  g_sumsq);
    cudaMemsetAsync(aggp, 0, (size_t)Nn * DD * sizeof(float));
    cudaMemsetAsync(csp,  0, DD * sizeof(float));
    cudaMemsetAsync(sqp,  0, sizeof(float));

    const int eblocks = (E + EB - 1) / EB;
    edge_kernel<<<eblocks, NTHR, SMEM_BYTES>>>(x, ea, ei, eW1, eb1, eW2, eb2, eg, ebt, eout, E);

    const int nblocks = (Nn + EB - 1) / EB;
    node_kernel<<<nblocks, NTHR, SMEM_BYTES>>>(x, nW1, nb1, nW2, nb2, ng, nbt, xout, Nn);

    rms_kernel<<<1, 128>>>(Nn);

    const int total = Nn * DD;
    finalize_kernel<<<(total + 255) / 256, 256>>>(xout, total);
}

// round 5
// speedup vs baseline: 3.3156x; 1.5773x over previous
#include <cuda_runtime.h>
#include <cuda_bf16.h>

#define DD   128
#define EB   128
#define NTHR 256
#define MAXN 100000

// ---- dynamic smem byte offsets -------------------------------------------
// GEMM1 phase: Ah 128x64 (stride 72) at OFF_A, Al at OFF_AL
// GEMM2 phase: Hh 128x128 (stride 136) at OFF_A, Hl at OFF_HL
// epilogue:    Hs 128x128 fp32 (stride 132) at OFF_A
// W chunk:     Wh 64x128 (stride 136) at OFF_W, Wl at OFF_WL
#define OFF_A    0
#define OFF_AL   18432
#define OFF_HL   34816
#define OFF_W    69632
#define OFF_WL   87040
#define OFF_TAIL 104448
#define SMEM_BYTES 105472

// ---- device global scratch (no runtime allocation allowed) ---------------
__device__ float g_agg[(size_t)MAXN * DD];
__device__ float g_colsum[DD];
__device__ float g_sumsq[1];
__device__ float g_mean[DD];
__device__ float g_invrms[1];
__device__ __nv_bfloat16 g_xh[(size_t)MAXN * DD];
__device__ __nv_bfloat16 g_xl[(size_t)MAXN * DD];
__device__ __nv_bfloat16 g_eW1h[3 * DD * DD], g_eW1l[3 * DD * DD];
__device__ __nv_bfloat16 g_eW2h[DD * DD],     g_eW2l[DD * DD];
__device__ __nv_bfloat16 g_nW1h[2 * DD * DD], g_nW1l[2 * DD * DD];
__device__ __nv_bfloat16 g_nW2h[DD * DD],     g_nW2l[DD * DD];

// ---- helpers --------------------------------------------------------------
static __device__ __forceinline__ void warp_red2(float& a, float& b) {
#pragma unroll
    for (int o = 16; o > 0; o >>= 1) {
        a += __shfl_xor_sync(0xffffffffu, a, o);
        b += __shfl_xor_sync(0xffffffffu, b, o);
    }
}

static __device__ __forceinline__ void ldsm4(unsigned r[4], unsigned addr) {
    asm volatile("ldmatrix.sync.aligned.m8n8.x4.shared.b16 {%0,%1,%2,%3}, [%4];\n"
                 : "=r"(r[0]), "=r"(r[1]), "=r"(r[2]), "=r"(r[3]) : "r"(addr));
}
static __device__ __forceinline__ void ldsm4t(unsigned r[4], unsigned addr) {
    asm volatile("ldmatrix.sync.aligned.m8n8.x4.trans.shared.b16 {%0,%1,%2,%3}, [%4];\n"
                 : "=r"(r[0]), "=r"(r[1]), "=r"(r[2]), "=r"(r[3]) : "r"(addr));
}
static __device__ __forceinline__ void mma16816(float d[4], const unsigned a[4],
                                                unsigned b0, unsigned b1) {
    asm volatile("mma.sync.aligned.m16n8k16.row.col.f32.bf16.bf16.f32 "
                 "{%0,%1,%2,%3}, {%4,%5,%6,%7}, {%8,%9}, {%0,%1,%2,%3};\n"
                 : "+f"(d[0]), "+f"(d[1]), "+f"(d[2]), "+f"(d[3])
                 : "r"(a[0]), "r"(a[1]), "r"(a[2]), "r"(a[3]), "r"(b0), "r"(b1));
}
static __device__ __forceinline__ void cp16(unsigned saddr, const void* gptr) {
    asm volatile("cp.async.cg.shared.global [%0], [%1], 16;\n" :: "r"(saddr), "l"(gptr));
}
static __device__ __forceinline__ void cp_commit() {
    asm volatile("cp.async.commit_group;\n");
}
static __device__ __forceinline__ void cp_wait0() {
    asm volatile("cp.async.wait_group 0;\n" ::: "memory");
}

// split fp32 float4 -> (hi, lo) bf16, store 4 elems at [r][c] with stride STR
template <int STR>
static __device__ __forceinline__ void split_store_s(__nv_bfloat16* H, __nv_bfloat16* L,
                                                     int r, int c, float4 v) {
    __nv_bfloat162 h01 = __floats2bfloat162_rn(v.x, v.y);
    __nv_bfloat162 h23 = __floats2bfloat162_rn(v.z, v.w);
    __nv_bfloat162 l01 = __floats2bfloat162_rn(v.x - __bfloat162float(h01.x),
                                               v.y - __bfloat162float(h01.y));
    __nv_bfloat162 l23 = __floats2bfloat162_rn(v.z - __bfloat162float(h23.x),
                                               v.w - __bfloat162float(h23.y));
    *(__nv_bfloat162*)(H + r * STR + c)     = h01;
    *(__nv_bfloat162*)(H + r * STR + c + 2) = h23;
    *(__nv_bfloat162*)(L + r * STR + c)     = l01;
    *(__nv_bfloat162*)(L + r * STR + c + 2) = l23;
}

// one K=64 chunk of 3-pass bf16-split MMA: acc += A(128x64) * B(64x128)
// A at ahB/alB (byte smem addrs), element stride astr, col offset acol0.
// W at whB/wlB, stride 136.
static __device__ __forceinline__ void mma_chunk64(float acc[2][8][4],
                                                   unsigned ahB, unsigned alB,
                                                   int astr, int acol0,
                                                   unsigned whB, unsigned wlB,
                                                   int wm, int wn, int lane) {
    const int ar  = lane & 15;
    const int asl = (lane >> 4) * 8;
#pragma unroll
    for (int ks = 0; ks < 4; ks++) {
        unsigned a_h[2][4], a_l[2][4];
        const int acol = acol0 + ks * 16 + asl;
#pragma unroll
        for (int mt = 0; mt < 2; mt++) {
            int arow = wm * 32 + mt * 16 + ar;
            unsigned off = (unsigned)((arow * astr + acol) * 2);
            ldsm4(a_h[mt], ahB + off);
            ldsm4(a_l[mt], alB + off);
        }
        const int brow = ks * 16 + ar;
#pragma unroll
        for (int np = 0; np < 4; np++) {
            int bcol = wn * 64 + np * 16 + asl;
            unsigned off = (unsigned)((brow * 136 + bcol) * 2);
            unsigned bh[4], bl[4];
            ldsm4t(bh, whB + off);
            ldsm4t(bl, wlB + off);
#pragma unroll
            for (int mt = 0; mt < 2; mt++) {
                mma16816(acc[mt][2 * np],     a_h[mt], bh[0], bh[1]);
                mma16816(acc[mt][2 * np],     a_h[mt], bl[0], bl[1]);
                mma16816(acc[mt][2 * np],     a_l[mt], bh[0], bh[1]);
                mma16816(acc[mt][2 * np + 1], a_h[mt], bh[2], bh[3]);
                mma16816(acc[mt][2 * np + 1], a_h[mt], bl[2], bl[3]);
                mma16816(acc[mt][2 * np + 1], a_l[mt], bh[2], bh[3]);
            }
        }
    }
}

// issue cp.async for one 64-row x 128-col weight chunk (hi+lo) into OFF_W/OFF_WL
static __device__ __forceinline__ void load_w64(unsigned sbase,
                                                const __nv_bfloat16* Wh,
                                                const __nv_bfloat16* Wl, int tid) {
#pragma unroll
    for (int i = 0; i < 4; i++) {
        int idx = tid + NTHR * i;
        int r = idx >> 4, u = (idx & 15) * 8;
        unsigned so = (unsigned)((r * 136 + u) * 2);
        cp16(sbase + OFF_W  + so, Wh + r * DD + u);
        cp16(sbase + OFF_WL + so, Wl + r * DD + u);
    }
}

// hidden epilogue: bias + relu, split to bf16 hi/lo at stride 136; zero acc
static __device__ __forceinline__ void hidden_split(float acc[2][8][4],
                                                    __nv_bfloat16* Hh, __nv_bfloat16* Hl,
                                                    const float* __restrict__ b1,
                                                    int wm, int wn, int lane) {
    const int g = lane >> 2, t = lane & 3;
#pragma unroll
    for (int mt = 0; mt < 2; mt++) {
#pragma unroll
        for (int nt = 0; nt < 8; nt++) {
            int col = wn * 64 + nt * 8 + t * 2;
            float bx = b1[col], by = b1[col + 1];
            int r0 = wm * 32 + mt * 16 + g;
            float h0 = fmaxf(acc[mt][nt][0] + bx, 0.f);
            float h1 = fmaxf(acc[mt][nt][1] + by, 0.f);
            float h2 = fmaxf(acc[mt][nt][2] + bx, 0.f);
            float h3 = fmaxf(acc[mt][nt][3] + by, 0.f);
            __nv_bfloat162 hh0 = __floats2bfloat162_rn(h0, h1);
            __nv_bfloat162 ll0 = __floats2bfloat162_rn(h0 - __bfloat162float(hh0.x),
                                                       h1 - __bfloat162float(hh0.y));
            *(__nv_bfloat162*)(Hh + r0 * 136 + col) = hh0;
            *(__nv_bfloat162*)(Hl + r0 * 136 + col) = ll0;
            __nv_bfloat162 hh1 = __floats2bfloat162_rn(h2, h3);
            __nv_bfloat162 ll1 = __floats2bfloat162_rn(h2 - __bfloat162float(hh1.x),
                                                       h3 - __bfloat162float(hh1.y));
            *(__nv_bfloat162*)(Hh + (r0 + 8) * 136 + col) = hh1;
            *(__nv_bfloat162*)(Hl + (r0 + 8) * 136 + col) = ll1;
            acc[mt][nt][0] = acc[mt][nt][1] = acc[mt][nt][2] = acc[mt][nt][3] = 0.f;
        }
    }
}

// write acc + b2 -> Hs fp32 (stride 132)
static __device__ __forceinline__ void out_store(const float acc[2][8][4], float* Hs,
                                                 const float* __restrict__ b2,
                                                 int wm, int wn, int lane) {
    const int g = lane >> 2, t = lane & 3;
#pragma unroll
    for (int mt = 0; mt < 2; mt++) {
#pragma unroll
        for (int nt = 0; nt < 8; nt++) {
            int col = wn * 64 + nt * 8 + t * 2;
            float bx = b2[col], by = b2[col + 1];
            int r0 = wm * 32 + mt * 16 + g;
            *(float2*)(Hs + r0 * 132 + col)       = make_float2(acc[mt][nt][0] + bx, acc[mt][nt][1] + by);
            *(float2*)(Hs + (r0 + 8) * 132 + col) = make_float2(acc[mt][nt][2] + bx, acc[mt][nt][3] + by);
        }
    }
}

// ---- prep: fp32 -> bf16 hi/lo split ---------------------------------------
__global__ void prep_split(const float* __restrict__ src, __nv_bfloat16* __restrict__ h,
                           __nv_bfloat16* __restrict__ l, int n4) {
    int i = blockIdx.x * blockDim.x + threadIdx.x;
    if (i >= n4) return;
    float4 v = ((const float4*)src)[i];
    __nv_bfloat162 h01 = __floats2bfloat162_rn(v.x, v.y);
    __nv_bfloat162 h23 = __floats2bfloat162_rn(v.z, v.w);
    __nv_bfloat162 l01 = __floats2bfloat162_rn(v.x - __bfloat162float(h01.x),
                                               v.y - __bfloat162float(h01.y));
    __nv_bfloat162 l23 = __floats2bfloat162_rn(v.z - __bfloat162float(h23.x),
                                               v.w - __bfloat162float(h23.y));
    ((__nv_bfloat162*)h)[2 * i]     = h01;
    ((__nv_bfloat162*)h)[2 * i + 1] = h23;
    ((__nv_bfloat162*)l)[2 * i]     = l01;
    ((__nv_bfloat162*)l)[2 * i + 1] = l23;
}

// ---------------------------------------------------------------------------
__global__ void __launch_bounds__(NTHR, 2)
edge_kernel(const float* __restrict__ ea,
            const int* __restrict__ ei,
            const float* __restrict__ b1, const float* __restrict__ b2,
            const float* __restrict__ gma, const float* __restrict__ bta,
            float* __restrict__ eout, int E)
{
    extern __shared__ char smc[];
    int* sIdx = (int*)(smc + OFF_TAIL);   // [0..127]=src, [128..255]=dst
    float* Hs = (float*)(smc + OFF_A);

    const int tid = threadIdx.x, lane = tid & 31, wid = tid >> 5;
    const int wm = wid & 3, wn = wid >> 2;
    const int eb = blockIdx.x * EB;
    const int Eloc = min(EB, E - eb);

    if (tid < 128) sIdx[tid] = (tid < Eloc) ? ei[eb + tid] : 0;
    else { int t2 = tid - 128; sIdx[tid] = (t2 < Eloc) ? ei[E + eb + t2] : 0; }
    __syncthreads();

    const unsigned sbase = (unsigned)__cvta_generic_to_shared(smc);

    float acc[2][8][4];
#pragma unroll
    for (int mt = 0; mt < 2; mt++)
#pragma unroll
        for (int nt = 0; nt < 8; nt++)
#pragma unroll
            for (int q = 0; q < 4; q++) acc[mt][nt][q] = 0.f;

    // ---- GEMM1: K=384 in 6 chunks of 64 ----
#pragma unroll 1
    for (int chunk = 0; chunk < 6; chunk++) {
        const int seg = chunk >> 1;
        const int c0  = (chunk & 1) * 64;

        load_w64(sbase, g_eW1h + chunk * 64 * DD, g_eW1l + chunk * 64 * DD, tid);

        if (seg < 2) {
            // gathered x rows: preconverted bf16 hi/lo via cp.async
#pragma unroll
            for (int i = 0; i < 4; i++) {
                int idx = tid + NTHR * i;
                int r = idx >> 3, u = (idx & 7) * 8;
                size_t grow = (size_t)sIdx[seg * 128 + r] * DD + c0 + u;
                unsigned so = (unsigned)((r * 72 + u) * 2);
                cp16(sbase + OFF_A  + so, g_xh + grow);
                cp16(sbase + OFF_AL + so, g_xl + grow);
            }
            cp_commit();
            cp_wait0();
        } else {
            cp_commit();
            // edge_attr fp32 -> split in registers
            __nv_bfloat16* Ah = (__nv_bfloat16*)(smc + OFF_A);
            __nv_bfloat16* Al = (__nv_bfloat16*)(smc + OFF_AL);
#pragma unroll
            for (int i = 0; i < 8; i++) {
                int idx = tid + NTHR * i;
                int r = idx >> 4, col = (idx & 15) * 4;
                if (r < Eloc) {
                    float4 v = *(const float4*)(ea + (size_t)(eb + r) * DD + c0 + col);
                    split_store_s<72>(Ah, Al, r, col, v);
                }
            }
            cp_wait0();
        }
        __syncthreads();
        mma_chunk64(acc, sbase + OFF_A, sbase + OFF_AL, 72, 0,
                    sbase + OFF_W, sbase + OFF_WL, wm, wn, lane);
        __syncthreads();
    }

    // ---- hidden: bias + relu -> bf16 hi/lo (stride 136) ----
    hidden_split(acc, (__nv_bfloat16*)(smc + OFF_A), (__nv_bfloat16*)(smc + OFF_HL),
                 b1, wm, wn, lane);

    // ---- GEMM2: K=128 in 2 chunks ----
#pragma unroll 1
    for (int chunk = 0; chunk < 2; chunk++) {
        load_w64(sbase, g_eW2h + chunk * 64 * DD, g_eW2l + chunk * 64 * DD, tid);
        cp_commit();
        cp_wait0();
        __syncthreads();   // also orders hidden_split writes before first MMA
        mma_chunk64(acc, sbase + OFF_A, sbase + OFF_HL, 136, chunk * 64,
                    sbase + OFF_W, sbase + OFF_WL, wm, wn, lane);
        __syncthreads();
    }

    out_store(acc, Hs, b2, wm, wn, lane);
    __syncthreads();

    // ---- LN + edge residual + scatter-add ----
#pragma unroll 1
    for (int j = 0; j < 16; j++) {
        int r = wid * 16 + j;            // warp-uniform
        if (r >= Eloc) continue;
        size_t ge = (size_t)(eb + r);
        float v[4], s = 0.f, sq = 0.f;
#pragma unroll
        for (int q = 0; q < 4; q++) {
            v[q] = Hs[r * 132 + lane + 32 * q];
            s += v[q]; sq += v[q] * v[q];
        }
        warp_red2(s, sq);
        float mu  = s * (1.f / 128.f);
        float var = sq * (1.f / 128.f) - mu * mu;
        float inv = rsqrtf(var + 1e-5f);
        size_t dn = (size_t)sIdx[128 + r];
#pragma unroll
        for (int q = 0; q < 4; q++) {
            int c = lane + 32 * q;
            float o = (v[q] - mu) * inv * gma[c] + bta[c];
            eout[ge * DD + c] = ea[ge * DD + c] + o;
            atomicAdd(&g_agg[dn * DD + c], o);
        }
    }
}

// ---------------------------------------------------------------------------
__global__ void __launch_bounds__(NTHR, 2)
node_kernel(const float* __restrict__ x,
            const float* __restrict__ b1, const float* __restrict__ b2,
            const float* __restrict__ gma, const float* __restrict__ bta,
            float* __restrict__ xpre, int Nn)
{
    extern __shared__ char smc[];
    float* csum_s = (float*)(smc + OFF_TAIL);    // 128 col sums + [128]=sumsq
    float* Hs = (float*)(smc + OFF_A);

    const int tid = threadIdx.x, lane = tid & 31, wid = tid >> 5;
    const int wm = wid & 3, wn = wid >> 2;
    const int nb = blockIdx.x * EB;
    const int Nloc = min(EB, Nn - nb);

    if (tid < 129) csum_s[tid] = 0.f;
    __syncthreads();

    const unsigned sbase = (unsigned)__cvta_generic_to_shared(smc);

    float acc[2][8][4];
#pragma unroll
    for (int mt = 0; mt < 2; mt++)
#pragma unroll
        for (int nt = 0; nt < 8; nt++)
#pragma unroll
            for (int q = 0; q < 4; q++) acc[mt][nt][q] = 0.f;

    // ---- GEMM1: K=256 in 4 chunks (x, x, agg, agg) ----
#pragma unroll 1
    for (int chunk = 0; chunk < 4; chunk++) {
        const int seg = chunk >> 1;
        const int c0  = (chunk & 1) * 64;

        load_w64(sbase, g_nW1h + chunk * 64 * DD, g_nW1l + chunk * 64 * DD, tid);

        if (seg == 0) {
#pragma unroll
            for (int i = 0; i < 4; i++) {
                int idx = tid + NTHR * i;
                int r = idx >> 3, u = (idx & 7) * 8;
                if (r < Nloc) {
                    size_t grow = (size_t)(nb + r) * DD + c0 + u;
                    unsigned so = (unsigned)((r * 72 + u) * 2);
                    cp16(sbase + OFF_A  + so, g_xh + grow);
                    cp16(sbase + OFF_AL + so, g_xl + grow);
                }
            }
            cp_commit();
            cp_wait0();
        } else {
            cp_commit();
            __nv_bfloat16* Ah = (__nv_bfloat16*)(smc + OFF_A);
            __nv_bfloat16* Al = (__nv_bfloat16*)(smc + OFF_AL);
#pragma unroll
            for (int i = 0; i < 8; i++) {
                int idx = tid + NTHR * i;
                int r = idx >> 4, col = (idx & 15) * 4;
                if (r < Nloc) {
                    float4 v = *(const float4*)(g_agg + (size_t)(nb + r) * DD + c0 + col);
                    split_store_s<72>(Ah, Al, r, col, v);
                }
            }
            cp_wait0();
        }
        __syncthreads();
        mma_chunk64(acc, sbase + OFF_A, sbase + OFF_AL, 72, 0,
                    sbase + OFF_W, sbase + OFF_WL, wm, wn, lane);
        __syncthreads();
    }

    hidden_split(acc, (__nv_bfloat16*)(smc + OFF_A), (__nv_bfloat16*)(smc + OFF_HL),
                 b1, wm, wn, lane);

#pragma unroll 1
    for (int chunk = 0; chunk < 2; chunk++) {
        load_w64(sbase, g_nW2h + chunk * 64 * DD, g_nW2l + chunk * 64 * DD, tid);
        cp_commit();
        cp_wait0();
        __syncthreads();
        mma_chunk64(acc, sbase + OFF_A, sbase + OFF_HL, 136, chunk * 64,
                    sbase + OFF_W, sbase + OFF_WL, wm, wn, lane);
        __syncthreads();
    }

    out_store(acc, Hs, b2, wm, wn, lane);
    __syncthreads();

    // ---- LN + residual + PairNorm partials ----
    float csum[4] = {0.f, 0.f, 0.f, 0.f};
    float sq_acc = 0.f;
#pragma unroll 1
    for (int j = 0; j < 16; j++) {
        int r = wid * 16 + j;
        if (r >= Nloc) continue;
        size_t gn = (size_t)(nb + r);
        float v[4], s = 0.f, sq = 0.f;
#pragma unroll
        for (int q = 0; q < 4; q++) {
            v[q] = Hs[r * 132 + lane + 32 * q];
            s += v[q]; sq += v[q] * v[q];
        }
        warp_red2(s, sq);
        float mu  = s * (1.f / 128.f);
        float var = sq * (1.f / 128.f) - mu * mu;
        float inv = rsqrtf(var + 1e-5f);
#pragma unroll
        for (int q = 0; q < 4; q++) {
            int c = lane + 32 * q;
            float o  = (v[q] - mu) * inv * gma[c] + bta[c];
            float xp = x[gn * DD + c] + o;
            xpre[gn * DD + c] = xp;
            csum[q] += xp;
            sq_acc  += xp * xp;
        }
    }
#pragma unroll
    for (int q = 0; q < 4; q++) atomicAdd(&csum_s[lane + 32 * q], csum[q]);
#pragma unroll
    for (int o = 16; o > 0; o >>= 1) sq_acc += __shfl_xor_sync(0xffffffffu, sq_acc, o);
    if (lane == 0) atomicAdd(&csum_s[128], sq_acc);
    __syncthreads();
    if (tid < 128)       atomicAdd(&g_colsum[tid], csum_s[tid]);
    else if (tid == 128) atomicAdd(&g_sumsq[0],    csum_s[128]);
}

// ---------------------------------------------------------------------------
__global__ void rms_kernel(int Nn)
{
    __shared__ float red[128];
    int c = threadIdx.x;
    float m = g_colsum[c] / (float)Nn;
    g_mean[c] = m;
    red[c] = m * m;
    __syncthreads();
    for (int o = 64; o > 0; o >>= 1) {
        if (c < o) red[c] += red[c + o];
        __syncthreads();
    }
    if (c == 0) {
        float ssc = g_sumsq[0] - (float)Nn * red[0];
        float rms = sqrtf(ssc / (float)Nn) + 1e-8f;
        g_invrms[0] = 1.0f / rms;
    }
}

__global__ void finalize_kernel(float* __restrict__ xout, int n4)
{
    int i = blockIdx.x * blockDim.x + threadIdx.x;
    if (i < n4) {
        float4 v = ((const float4*)xout)[i];
        int c = (i * 4) & 127;
        float inv = g_invrms[0];
        v.x = (v.x - g_mean[c])     * inv;
        v.y = (v.y - g_mean[c + 1]) * inv;
        v.z = (v.z - g_mean[c + 2]) * inv;
        v.w = (v.w - g_mean[c + 3]) * inv;
        ((float4*)xout)[i] = v;
    }
}

// ---------------------------------------------------------------------------
extern "C" void kernel_launch(void* const* d_in, const int* in_sizes, int n_in,
                              void* d_out, int out_size)
{
    const float* x   = (const float*)d_in[0];
    const float* ea  = (const float*)d_in[1];
    const int*   ei  = (const int*)d_in[2];      // edge_index: int32 (JAX x64 disabled)
    const float* eW1 = (const float*)d_in[3];
    const float* eb1 = (const float*)d_in[4];
    const float* eW2 = (const float*)d_in[5];
    const float* eb2 = (const float*)d_in[6];
    const float* eg  = (const float*)d_in[7];
    const float* ebt = (const float*)d_in[8];
    const float* nW1 = (const float*)d_in[9];
    const float* nb1 = (const float*)d_in[10];
    const float* nW2 = (const float*)d_in[11];
    const float* nb2 = (const float*)d_in[12];
    const float* ng  = (const float*)d_in[13];
    const float* nbt = (const float*)d_in[14];

    const int Nn = in_sizes[0] / DD;
    const int E  = in_sizes[1] / DD;

    float* xout = (float*)d_out;              // [Nn * D]
    float* eout = xout + (size_t)Nn * DD;     // [E * D]

    cudaFuncSetAttribute(edge_kernel, cudaFuncAttributeMaxDynamicSharedMemorySize, SMEM_BYTES);
    cudaFuncSetAttribute(node_kernel, cudaFuncAttributeMaxDynamicSharedMemorySize, SMEM_BYTES);

    void *aggp, *csp, *sqp;
    void *xhp, *xlp, *ew1h, *ew1l, *ew2h, *ew2l, *nw1h, *nw1l, *nw2h, *nw2l;
    cudaGetSymbolAddress(&aggp, g_agg);
    cudaGetSymbolAddress(&csp,  g_colsum);
    cudaGetSymbolAddress(&sqp,  g_sumsq);
    cudaGetSymbolAddress(&xhp,  g_xh);
    cudaGetSymbolAddress(&xlp,  g_xl);
    cudaGetSymbolAddress(&ew1h, g_eW1h);
    cudaGetSymbolAddress(&ew1l, g_eW1l);
    cudaGetSymbolAddress(&ew2h, g_eW2h);
    cudaGetSymbolAddress(&ew2l, g_eW2l);
    cudaGetSymbolAddress(&nw1h, g_nW1h);
    cudaGetSymbolAddress(&nw1l, g_nW1l);
    cudaGetSymbolAddress(&nw2h, g_nW2h);
    cudaGetSymbolAddress(&nw2l, g_nW2l);

    cudaMemsetAsync(aggp, 0, (size_t)Nn * DD * sizeof(float));
    cudaMemsetAsync(csp,  0, DD * sizeof(float));
    cudaMemsetAsync(sqp,  0, sizeof(float));

    // preconvert x and weights to bf16 hi/lo
    {
        int n4 = Nn * DD / 4;
        prep_split<<<(n4 + 255) / 256, 256>>>(x, (__nv_bfloat16*)xhp, (__nv_bfloat16*)xlp, n4);
        int w1 = 3 * DD * DD / 4;
        prep_split<<<(w1 + 255) / 256, 256>>>(eW1, (__nv_bfloat16*)ew1h, (__nv_bfloat16*)ew1l, w1);
        int w2 = DD * DD / 4;
        prep_split<<<(w2 + 255) / 256, 256>>>(eW2, (__nv_bfloat16*)ew2h, (__nv_bfloat16*)ew2l, w2);
        int w3 = 2 * DD * DD / 4;
        prep_split<<<(w3 + 255) / 256, 256>>>(nW1, (__nv_bfloat16*)nw1h, (__nv_bfloat16*)nw1l, w3);
        prep_split<<<(w2 + 255) / 256, 256>>>(nW2, (__nv_bfloat16*)nw2h, (__nv_bfloat16*)nw2l, w2);
    }

    const int eblocks = (E + EB - 1) / EB;
    edge_kernel<<<eblocks, NTHR, SMEM_BYTES>>>(ea, ei, eb1, eb2, eg, ebt, eout, E);

    const int nblocks = (Nn + EB - 1) / EB;
    node_kernel<<<nblocks, NTHR, SMEM_BYTES>>>(x, nb1, nb2, ng, nbt, xout, Nn);

    rms_kernel<<<1, 128>>>(Nn);

    const int n4 = Nn * DD / 4;
    finalize_kernel<<<(n4 + 255) / 256, 256>>>(xout, n4);
}